// round 15
// baseline (speedup 1.0000x reference)
#include <cuda_runtime.h>
#include <math.h>
#include <stdint.h>

#define NN 100000
#define EE 1600000
#define XW 36     // Xr tile row stride (words): (4*ar+ac)%32 conflict-free
#define FB 8704   // words per buffer: Wpack(4096) + Xr(128*36=4608)
#define OF_XR 4096
#define SMF_TOTAL (2 * FB)   // 17,408 words = 69,632 B -> 2 blocks/SM
#define SP 68     // staging plane row stride (words): conflict-free

// -------- scratch (device globals; no allocation allowed) --------
// X operands stored as split planes: word = bf16x2 of (k_even, k_odd); hi & lo.
__device__ uint32_t g_fH[(size_t)NN * 32],  g_fL[(size_t)NN * 32];    // feat
__device__ uint32_t g_h1H[(size_t)NN * 64], g_h1L[(size_t)NN * 64];
__device__ uint32_t g_h2H[(size_t)NN * 64], g_h2L[(size_t)NN * 64];
__device__ uint32_t g_agH[(size_t)NN * 64], g_agL[(size_t)NN * 64];
__device__ float g_wp[92160];   // frag-major packed bf16 hi/lo of [W1|W2|Wm1|Wm2]
__device__ int   g_deg[NN];
__device__ int   g_off[NN];
__device__ int   g_cur[NN];
__device__ int   g_csr[EE];
__device__ int   g_bsum[512];

// -------- helpers --------
__device__ __forceinline__ float sigmoidf_(float x) {
    return 1.0f / (1.0f + __expf(-x));
}
// split float2 into packed bf16x2 hi + bf16x2 lo (element0 -> lower half)
__device__ __forceinline__ void split2(float2 v, uint32_t& hp, uint32_t& lp) {
    asm("cvt.rn.bf16x2.f32 %0, %1, %2;" : "=r"(hp) : "f"(v.y), "f"(v.x));
    float hx = __uint_as_float(hp << 16);
    float hy = __uint_as_float(hp & 0xffff0000u);
    float lx = v.x - hx, ly = v.y - hy;
    asm("cvt.rn.bf16x2.f32 %0, %1, %2;" : "=r"(lp) : "f"(ly), "f"(lx));
}
// decode word -> (even, odd) floats
__device__ __forceinline__ float2 dec2(uint32_t w) {
    return make_float2(__uint_as_float(w << 16), __uint_as_float(w & 0xffff0000u));
}
// D += A(16x16 bf16) * B(16x8 bf16), fp32 accumulate
__device__ __forceinline__ void mma_bf16(float4& d, const uint32_t* a, uint32_t b0, uint32_t b1) {
    asm("mma.sync.aligned.m16n8k16.row.col.f32.bf16.bf16.f32 "
        "{%0,%1,%2,%3}, {%4,%5,%6,%7}, {%8,%9}, {%0,%1,%2,%3};"
        : "+f"(d.x), "+f"(d.y), "+f"(d.z), "+f"(d.w)
        : "r"(a[0]), "r"(a[1]), "r"(a[2]), "r"(a[3]), "r"(b0), "r"(b1));
}
__device__ __forceinline__ void cpasync16(uint32_t dst, const void* src, int srcsize) {
    asm volatile("cp.async.ca.shared.global [%0], [%1], 16, %2;"
                 :: "r"(dst), "l"(src), "r"(srcsize) : "memory");
}
#define CP_COMMIT() asm volatile("cp.async.commit_group;" ::: "memory")
#define CP_WAIT1()  asm volatile("cp.async.wait_group 1;" ::: "memory")

// ============================================================================
// prep: zero deg, split feat into planes, pack weights frag-major (bf16 hi/lo)
// wp: W1 f4 [0,4096); W2 [4096,12288); Wm1 [12288,20480); Wm2 [20480,23040)
// ============================================================================
__global__ void prep1_kernel(int* __restrict__ deg, int n,
                             const float* __restrict__ feat,
                             uint32_t* __restrict__ fH, uint32_t* __restrict__ fL,
                             const float* __restrict__ W1,
                             const float* __restrict__ W2,
                             const float* __restrict__ Wm1,
                             const float* __restrict__ Wm2,
                             float* __restrict__ wp)
{
    int idx = blockIdx.x * blockDim.x + threadIdx.x;
    int stride = gridDim.x * blockDim.x;
    for (int i = idx; i < n; i += stride) deg[i] = 0;
    // feat -> split planes (word i = node i>>5, word i&31 = k pair)
    int nw = n * 32;
    for (int i = idx; i < nw; i += stride) {
        int node = i >> 5, w = i & 31;
        float2 v = *(const float2*)(feat + (size_t)node * 64 + 2 * w);
        uint32_t hp, lp;
        split2(v, hp, lp);
        fH[i] = hp; fL[i] = lp;
    }
    float4* wp4 = (float4*)wp;
    for (int i = idx; i < 23040; i += stride) {
        const float* W; int rs, k0, j;
        if (i < 20480) {
            int jb = 0, local;
            if (i < 4096)        { local = i;          W = W1;  rs = 128; }
            else if (i < 12288)  { local = i - 4096;   W = W2;  rs = 128; }
            else                 { local = i - 12288;  jb = local >> 12; local &= 4095; W = Wm1; rs = 256; }
            int c   = local >> 10;
            int s   = (local >> 9) & 1;
            int wn2 = (local >> 8) & 1;
            int nt  = (local >> 5) & 7;
            int l   = local & 31;
            k0 = c * 32 + s * 16 + 2 * (l & 3);
            j  = jb * 128 + wn2 * 64 + nt * 8 + (l >> 2);
        } else {
            int local = i - 20480;          // [sg(16)][nt(5)][lane(32)]
            int sg  = local / 160;
            int rem = local - sg * 160;
            int nt  = rem >> 5;
            int l   = rem & 31;
            W = Wm2; rs = 40;
            k0 = sg * 16 + 2 * (l & 3);
            j  = nt * 8 + (l >> 2);
        }
        float v00 = W[(size_t)k0 * rs + j];
        float v01 = W[(size_t)(k0 + 1) * rs + j];
        float v10 = W[(size_t)(k0 + 8) * rs + j];
        float v11 = W[(size_t)(k0 + 9) * rs + j];
        uint32_t w0, w2, w1, w3;
        split2(make_float2(v00, v01), w0, w2);
        split2(make_float2(v10, v11), w1, w3);
        wp4[i] = make_float4(__uint_as_float(w0), __uint_as_float(w1),
                             __uint_as_float(w2), __uint_as_float(w3));
    }
}

// -------- CSR build: histogram over dst --------
__global__ void hist_kernel(const int* __restrict__ ei, int* __restrict__ deg,
                            int E, int nNodes) {
    int e = blockIdx.x * blockDim.x + threadIdx.x;
    if (e >= E) return;
    int d = ei[E + e];
    if ((unsigned)d < (unsigned)nNodes) atomicAdd(&deg[d], 1);
}

// -------- scan phase 1: per-block inclusive scan; bsum = raw block totals ----
__global__ void scan1_kernel(const int* __restrict__ deg, int* __restrict__ off,
                             int* __restrict__ bsum, int n) {
    __shared__ int sh[1024];
    int tid = threadIdx.x;
    int i = blockIdx.x * 1024 + tid;
    int v = (i < n) ? deg[i] : 0;
    sh[tid] = v;
    __syncthreads();
    #pragma unroll
    for (int d = 1; d < 1024; d <<= 1) {
        int t = (tid >= d) ? sh[tid - d] : 0;
        __syncthreads();
        sh[tid] += t;
        __syncthreads();
    }
    if (i < n) off[i] = sh[tid] - v;
    if (tid == 1023) bsum[blockIdx.x] = sh[1023];
}

// -------- scan phase 2+3 fused: block computes its own bsum prefix ----------
__global__ void scan3_kernel(int* __restrict__ off, int* __restrict__ cur,
                             const int* __restrict__ bsum, int n) {
    __shared__ int red[32];
    __shared__ int sAdd;
    int tid = threadIdx.x;
    int acc = (tid < blockIdx.x) ? bsum[tid] : 0;   // nb <= 1024
    #pragma unroll
    for (int o = 16; o; o >>= 1) acc += __shfl_down_sync(~0u, acc, o);
    if ((tid & 31) == 0) red[tid >> 5] = acc;
    __syncthreads();
    if (tid == 0) {
        int s = 0;
        #pragma unroll
        for (int w = 0; w < 32; ++w) s += red[w];
        sAdd = s;
    }
    __syncthreads();
    int i = blockIdx.x * 1024 + tid;
    if (i < n) {
        int o = off[i] + sAdd;
        off[i] = o;
        cur[i] = o;
    }
}

// -------- CSR placement --------
__global__ void place_kernel(const int* __restrict__ ei, int* __restrict__ cur,
                             int* __restrict__ csr, int E, int nNodes) {
    int e = blockIdx.x * blockDim.x + threadIdx.x;
    if (e >= E) return;
    int s = ei[e];
    int d = ei[E + e];
    if ((unsigned)s >= (unsigned)nNodes || (unsigned)d >= (unsigned)nNodes) return;
    int pos = atomicAdd(&cur[d], 1);
    csr[pos] = s;
}

// -------- gather aggregate (plane in, plane out): warp per node --------
// x rowW=32 words (feat). agg written at rowW=32.
__global__ void __launch_bounds__(256) gather64_kernel(
    const int* __restrict__ off, const int* __restrict__ deg,
    const int* __restrict__ csr,
    const uint32_t* __restrict__ xH, const uint32_t* __restrict__ xL,
    uint32_t* __restrict__ aH, uint32_t* __restrict__ aL, int nNodes)
{
    int node = blockIdx.x * 8 + (threadIdx.x >> 5);
    if (node >= nNodes) return;
    int lane = threadIdx.x & 31;
    int beg = off[node], dg = deg[node];
    float2 acc = make_float2(0.f, 0.f);
    for (int e = beg; e < beg + dg; ++e) {
        int s = csr[e];
        float2 h = dec2(xH[(size_t)s * 32 + lane]);
        float2 l = dec2(xL[(size_t)s * 32 + lane]);
        acc.x += h.x + l.x;
        acc.y += h.y + l.y;
    }
    float sc = 1.0f / (float)max(dg, 1);
    acc.x *= sc; acc.y *= sc;
    uint32_t hp, lp;
    split2(acc, hp, lp);
    aH[(size_t)node * 32 + lane] = hp;
    aL[(size_t)node * 32 + lane] = lp;
}

// x rowW=64 words (h1). agg written at rowW=64.
__global__ void __launch_bounds__(256) gather128_kernel(
    const int* __restrict__ off, const int* __restrict__ deg,
    const int* __restrict__ csr,
    const uint32_t* __restrict__ xH, const uint32_t* __restrict__ xL,
    uint32_t* __restrict__ aH, uint32_t* __restrict__ aL, int nNodes)
{
    int node = blockIdx.x * 8 + (threadIdx.x >> 5);
    if (node >= nNodes) return;
    int lane = threadIdx.x & 31;
    int beg = off[node], dg = deg[node];
    float2 a0 = make_float2(0.f, 0.f), a1 = make_float2(0.f, 0.f);
    for (int e = beg; e < beg + dg; ++e) {
        int s = csr[e];
        const uint32_t* rh = xH + (size_t)s * 64 + lane;
        const uint32_t* rl = xL + (size_t)s * 64 + lane;
        float2 h0 = dec2(rh[0]),  l0 = dec2(rl[0]);
        float2 h1 = dec2(rh[32]), l1 = dec2(rl[32]);
        a0.x += h0.x + l0.x; a0.y += h0.y + l0.y;
        a1.x += h1.x + l1.x; a1.y += h1.y + l1.y;
    }
    float sc = 1.0f / (float)max(dg, 1);
    a0.x *= sc; a0.y *= sc; a1.x *= sc; a1.y *= sc;
    uint32_t hp, lp;
    split2(a0, hp, lp);
    aH[(size_t)node * 64 + lane] = hp;
    aL[(size_t)node * 64 + lane] = lp;
    split2(a1, hp, lp);
    aH[(size_t)node * 64 + lane + 32] = hp;
    aL[(size_t)node * 64 + lane + 32] = lp;
}

// ============================================================================
// GEMM mainloop body: one 32-k chunk (2 k16-steps) from buffer {Wpack, Xw}.
// A-feed: 16 scalar LDS of pre-split words per step — ZERO cvt in mainloop.
// Xw layout per node row (stride 36 words): hi words 0..15, lo words 16..31.
// ============================================================================
__device__ __forceinline__ void mma_chunk(
    const float* Wp, const uint32_t* Xw,
    int wm, int wn2, int lane, float4 C0[8], float4 C1[8])
{
    const int ar = lane >> 2, ac = lane & 3;
    #pragma unroll
    for (int s = 0; s < 2; ++s) {
        uint32_t Ah[2][4], Al[2][4];
        #pragma unroll
        for (int mt = 0; mt < 2; ++mt) {
            int nb = wm + mt * 16 + ar;
            const uint32_t* xp = Xw + nb * XW + s * 8 + ac;
            const uint32_t* xq = xp + 8 * XW;
            Ah[mt][0] = xp[0];  Ah[mt][1] = xq[0];
            Ah[mt][2] = xp[4];  Ah[mt][3] = xq[4];
            Al[mt][0] = xp[16]; Al[mt][1] = xq[16];
            Al[mt][2] = xp[20]; Al[mt][3] = xq[20];
        }
        const float4* bp = (const float4*)Wp + ((s * 2 + wn2) * 8) * 32 + lane;
        #pragma unroll
        for (int nt = 0; nt < 8; ++nt) {
            float4 bw = bp[nt * 32];
            uint32_t bh0 = __float_as_uint(bw.x), bh1 = __float_as_uint(bw.y);
            uint32_t bl0 = __float_as_uint(bw.z), bl1 = __float_as_uint(bw.w);
            mma_bf16(C0[nt], Ah[0], bh0, bh1);
            mma_bf16(C1[nt], Ah[1], bh0, bh1);
            mma_bf16(C0[nt], Al[0], bh0, bh1);
            mma_bf16(C1[nt], Al[1], bh0, bh1);
            mma_bf16(C0[nt], Ah[0], bl0, bl1);
            mma_bf16(C1[nt], Ah[1], bl0, bl1);
        }
    }
}

// ============================================================================
// combine: out_planes = split(sigmoid(concat(self, agg) @ W + b))
// Inputs/outputs all in split-plane format. ROWW = K/4 words per plane row.
// ============================================================================
template<int K>
__global__ void __launch_bounds__(256, 2) combine_kernel(
    const uint32_t* __restrict__ selfH, const uint32_t* __restrict__ selfL,
    const uint32_t* __restrict__ aggH,  const uint32_t* __restrict__ aggL,
    const float* __restrict__ wpG, const float* __restrict__ b,
    uint32_t* __restrict__ outH, uint32_t* __restrict__ outL, int nNodes)
{
    constexpr int NCH = K / 32;
    constexpr int ROWW = K / 4;
    extern __shared__ float smf[];
    const uint32_t smBase = (uint32_t)__cvta_generic_to_shared(smf);

    const int t = threadIdx.x;
    const int lane = t & 31, warp = t >> 5;
    const int wm = (warp & 3) * 32;
    const int wn2 = warp >> 2;
    const int wn = wn2 * 64;
    const int base = blockIdx.x * 128;
    const int ar = lane >> 2, ac = lane & 3;

    float4 C0[8], C1[8];
    #pragma unroll
    for (int nt = 0; nt < 8; ++nt) {
        int j = wn + nt * 8 + 2 * ac;
        float bx = b[j], by = b[j + 1];
        C0[nt] = make_float4(bx, by, bx, by);
        C1[nt] = make_float4(bx, by, bx, by);
    }

    auto prefetch = [&](int ch, int buf) {
        const uint32_t bb = smBase + (uint32_t)(buf * FB) * 4;
        int g = t & 7;
        bool isAgg = (ch >= NCH / 2);
        int w0 = (isAgg ? ch - NCH / 2 : ch) * 16;
        const uint32_t* pl = (g < 4) ? (isAgg ? aggH : selfH) : (isAgg ? aggL : selfL);
        int gw = (g & 3) * 4;
        const uint32_t* src0 = pl + w0 + gw;
        int col = (g < 4) ? gw : 16 + gw;
        #pragma unroll
        for (int it = 0; it < 4; ++it) {
            int n = (t >> 3) + 32 * it;
            int ngl = base + n;
            int sz = (ngl < nNodes) ? 16 : 0;
            cpasync16(bb + (uint32_t)(OF_XR + n * XW + col) * 4,
                      src0 + (size_t)ngl * ROWW, sz);
        }
        const float* wsrc = wpG + (size_t)ch * 4096;
        #pragma unroll
        for (int r = 0; r < 4; ++r) {
            int i = t + 256 * r;
            cpasync16(bb + (uint32_t)(i * 4) * 4, wsrc + i * 4, 16);
        }
    };

    prefetch(0, 0); CP_COMMIT();

    for (int ch = 0; ch < NCH; ++ch) {
        __syncthreads();
        if (ch + 1 < NCH) prefetch(ch + 1, (ch + 1) & 1);
        CP_COMMIT();
        CP_WAIT1();
        __syncthreads();
        const float* bufp = smf + (ch & 1) * FB;
        mma_chunk(bufp, (const uint32_t*)(bufp + OF_XR), wm, wn2, lane, C0, C1);
    }
    __syncthreads();   // buffers free; reuse smem as split staging planes

    uint32_t* Rsh = (uint32_t*)smf;        // [128][SP]
    uint32_t* Rsl = Rsh + 128 * SP;        // [128][SP]
    #pragma unroll
    for (int mt = 0; mt < 2; ++mt) {
        int row = wm + mt * 16 + ar;
        float4* Cm = (mt == 0) ? C0 : C1;
        #pragma unroll
        for (int nt = 0; nt < 8; ++nt) {
            int colw = (wn >> 1) + nt * 4 + ac;
            float4 c = Cm[nt];
            uint32_t hp, lp;
            split2(make_float2(sigmoidf_(c.x), sigmoidf_(c.y)), hp, lp);
            Rsh[row * SP + colw] = hp; Rsl[row * SP + colw] = lp;
            split2(make_float2(sigmoidf_(c.z), sigmoidf_(c.w)), hp, lp);
            Rsh[(row + 8) * SP + colw] = hp; Rsl[(row + 8) * SP + colw] = lp;
        }
    }
    __syncthreads();

    if (base + 128 <= nNodes) {
        for (int i = t; i < 128 * 16; i += 256) {
            int n = i >> 4, q = (i & 15) * 4;
            *(float4*)(outH + (size_t)(base + n) * 64 + q) = *(const float4*)(Rsh + n * SP + q);
            *(float4*)(outL + (size_t)(base + n) * 64 + q) = *(const float4*)(Rsl + n * SP + q);
        }
    } else {
        for (int i = t; i < 128 * 64; i += 256) {
            int n = i >> 6, w = i & 63;
            if (base + n < nNodes) {
                outH[(size_t)(base + n) * 64 + w] = Rsh[n * SP + w];
                outL[(size_t)(base + n) * 64 + w] = Rsl[n * SP + w];
            }
        }
    }
}

// ============================================================================
// mlp fused: out = relu(h2 @ Wm1 + bm1) @ Wm2 + bm2
// h2 in split planes; hidden staged as split planes (relu pre-split);
// stage-2 A-feed is raw word LDS, zero cvt.
// ============================================================================
__global__ void __launch_bounds__(256, 2) mlp_fused_kernel(
    const uint32_t* __restrict__ h2H, const uint32_t* __restrict__ h2L,
    const float* __restrict__ wpG,    // packed Wm1 (2 jb blobs of 16384 floats)
    const float* __restrict__ bm1,    // [256]
    const float* __restrict__ wp2G,   // packed Wm2 [16 sg][5 nt][32 lane] float4
    const float* __restrict__ bm2,    // [40]
    float* __restrict__ out,          // [N, 40]
    int nNodes)
{
    extern __shared__ float smf[];
    const uint32_t smBase = (uint32_t)__cvta_generic_to_shared(smf);

    const int t = threadIdx.x;
    const int lane = t & 31, warp = t >> 5;
    const int wm = (warp & 3) * 32;
    const int wn2 = warp >> 2;
    const int wn = wn2 * 64;
    const int base = blockIdx.x * 128;
    const int ar = lane >> 2, ac = lane & 3;

    auto prefetch = [&](int pass, int ch, int buf) {
        const uint32_t bb = smBase + (uint32_t)(buf * FB) * 4;
        int g = t & 7;
        int w0 = ch * 16;
        const uint32_t* pl = (g < 4) ? h2H : h2L;
        int gw = (g & 3) * 4;
        const uint32_t* src0 = pl + w0 + gw;
        int col = (g < 4) ? gw : 16 + gw;
        #pragma unroll
        for (int it = 0; it < 4; ++it) {
            int n = (t >> 3) + 32 * it;
            int ngl = base + n;
            int sz = (ngl < nNodes) ? 16 : 0;
            cpasync16(bb + (uint32_t)(OF_XR + n * XW + col) * 4,
                      src0 + (size_t)ngl * 64, sz);
        }
        const float* wsrc = wpG + (size_t)pass * 16384 + (size_t)ch * 4096;
        #pragma unroll
        for (int r = 0; r < 4; ++r) {
            int i = t + 256 * r;
            cpasync16(bb + (uint32_t)(i * 4) * 4, wsrc + i * 4, 16);
        }
    };

    // persistent output accumulators: 16 nodes x 40 outs per warp
    float4 O[5];
    #pragma unroll
    for (int nt = 0; nt < 5; ++nt) {
        int j = nt * 8 + 2 * ac;
        float bx = bm2[j], by = bm2[j + 1];
        O[nt] = make_float4(bx, by, bx, by);
    }

    for (int pass = 0; pass < 2; ++pass) {
        float4 C0[8], C1[8];
        #pragma unroll
        for (int nt = 0; nt < 8; ++nt) {
            int j = pass * 128 + wn + nt * 8 + 2 * ac;
            float bx = bm1[j], by = bm1[j + 1];
            C0[nt] = make_float4(bx, by, bx, by);
            C1[nt] = make_float4(bx, by, bx, by);
        }

        prefetch(pass, 0, 0); CP_COMMIT();
        for (int ch = 0; ch < 4; ++ch) {
            __syncthreads();
            if (ch + 1 < 4) prefetch(pass, ch + 1, (ch + 1) & 1);
            CP_COMMIT();
            CP_WAIT1();
            __syncthreads();
            const float* bufp = smf + (ch & 1) * FB;
            mma_chunk(bufp, (const uint32_t*)(bufp + OF_XR), wm, wn2, lane, C0, C1);
        }
        __syncthreads();   // pipeline drained; stage hidden as split planes

        uint32_t* Rsh = (uint32_t*)smf;    // [128 node][SP] node-major!
        uint32_t* Rsl = Rsh + 128 * SP;
        #pragma unroll
        for (int mt = 0; mt < 2; ++mt) {
            int row = wm + mt * 16 + ar;
            float4* Cm = (mt == 0) ? C0 : C1;
            #pragma unroll
            for (int nt = 0; nt < 8; ++nt) {
                int colw = (wn >> 1) + nt * 4 + ac;
                float4 c = Cm[nt];
                uint32_t hp, lp;
                split2(make_float2(fmaxf(c.x, 0.f), fmaxf(c.y, 0.f)), hp, lp);
                Rsh[row * SP + colw] = hp; Rsl[row * SP + colw] = lp;
                split2(make_float2(fmaxf(c.z, 0.f), fmaxf(c.w, 0.f)), hp, lp);
                Rsh[(row + 8) * SP + colw] = hp; Rsl[(row + 8) * SP + colw] = lp;
            }
        }
        __syncthreads();

        // ---- second GEMM: O += hidden(this pass's 128 k) @ Wm2 ----
        {
            const int n0 = warp * 16 + ar;
            const float4* wp2f = (const float4*)wp2G;
            #pragma unroll
            for (int s8 = 0; s8 < 8; ++s8) {
                const uint32_t* xp = Rsh + n0 * SP + s8 * 8 + ac;
                const uint32_t* xq = xp + 8 * SP;
                const uint32_t* yp = Rsl + n0 * SP + s8 * 8 + ac;
                const uint32_t* yq = yp + 8 * SP;
                uint32_t Ah[4] = { xp[0], xq[0], xp[4], xq[4] };
                uint32_t Al[4] = { yp[0], yq[0], yp[4], yq[4] };
                const int sg = pass * 8 + s8;
                #pragma unroll
                for (int nt = 0; nt < 5; ++nt) {
                    float4 bw = __ldg(wp2f + (sg * 5 + nt) * 32 + lane);
                    uint32_t bh0 = __float_as_uint(bw.x), bh1 = __float_as_uint(bw.y);
                    uint32_t bl0 = __float_as_uint(bw.z), bl1 = __float_as_uint(bw.w);
                    mma_bf16(O[nt], Ah, bh0, bh1);
                    mma_bf16(O[nt], Al, bh0, bh1);
                    mma_bf16(O[nt], Ah, bl0, bl1);
                }
            }
        }
        __syncthreads();   // stage-2 reads done before next pass's prefetch
    }

    // ---- final epilogue: stage O [128 node][44], coalesced write ----
    float* Os = smf;
    {
        const int n0 = warp * 16 + ar;
        #pragma unroll
        for (int nt = 0; nt < 5; ++nt) {
            int col = nt * 8 + 2 * ac;
            *(float2*)(Os + n0 * 44 + col)       = make_float2(O[nt].x, O[nt].y);
            *(float2*)(Os + (n0 + 8) * 44 + col) = make_float2(O[nt].z, O[nt].w);
        }
    }
    __syncthreads();

    const float4* Os4 = (const float4*)Os;
    float4* out4 = (float4*)out;
    for (int i = t; i < 128 * 10; i += 256) {
        int n = i / 10, q = i - n * 10;
        int ngl = base + n;
        if (ngl < nNodes) out4[(size_t)ngl * 10 + q] = Os4[n * 11 + q];
    }
}

// -------- launch --------
extern "C" void kernel_launch(void* const* d_in, const int* in_sizes, int n_in,
                              void* d_out, int out_size)
{
    const float* feat = (const float*)d_in[0];
    const int*   ei   = (const int*)d_in[1];     // int32 (JAX x64 disabled)
    const float* W1  = (const float*)d_in[2];
    const float* b1  = (const float*)d_in[3];
    const float* W2  = (const float*)d_in[4];
    const float* b2  = (const float*)d_in[5];
    const float* Wm1 = (const float*)d_in[6];
    const float* bm1 = (const float*)d_in[7];
    const float* Wm2 = (const float*)d_in[8];
    const float* bm2 = (const float*)d_in[9];
    float* out = (float*)d_out;

    const int N = in_sizes[0] / 64;     // 100000
    const int E = in_sizes[1] / 2;      // 1600000

    uint32_t *fH, *fL, *h1H, *h1L, *h2H, *h2L, *agH, *agL;
    float *wp;
    int *deg, *off, *cur, *csr, *bsum;
    cudaGetSymbolAddress((void**)&fH,  g_fH);
    cudaGetSymbolAddress((void**)&fL,  g_fL);
    cudaGetSymbolAddress((void**)&h1H, g_h1H);
    cudaGetSymbolAddress((void**)&h1L, g_h1L);
    cudaGetSymbolAddress((void**)&h2H, g_h2H);
    cudaGetSymbolAddress((void**)&h2L, g_h2L);
    cudaGetSymbolAddress((void**)&agH, g_agH);
    cudaGetSymbolAddress((void**)&agL, g_agL);
    cudaGetSymbolAddress((void**)&wp,  g_wp);
    cudaGetSymbolAddress((void**)&deg, g_deg);
    cudaGetSymbolAddress((void**)&off, g_off);
    cudaGetSymbolAddress((void**)&cur, g_cur);
    cudaGetSymbolAddress((void**)&csr, g_csr);
    cudaGetSymbolAddress((void**)&bsum, g_bsum);

    const int SM_GEMM = SMF_TOTAL * 4;   // 69,632 B -> 2 blocks/SM
    cudaFuncSetAttribute(combine_kernel<128>, cudaFuncAttributeMaxDynamicSharedMemorySize, SM_GEMM);
    cudaFuncSetAttribute(combine_kernel<256>, cudaFuncAttributeMaxDynamicSharedMemorySize, SM_GEMM);
    cudaFuncSetAttribute(mlp_fused_kernel,    cudaFuncAttributeMaxDynamicSharedMemorySize, SM_GEMM);

    const int nodeBlocks = (N + 127) / 128;      // 782
    const int gatherBlocks = (N + 7) / 8;        // 12500
    const int scanBlocks = (N + 1023) / 1024;    // 98
    const int edgeBlocks = (E + 255) / 256;

    // ---- prep (deg zero + feat split + W pack) & CSR build ----
    prep1_kernel<<<2048, 256>>>(deg, N, feat, fH, fL, W1, W2, Wm1, Wm2, wp);
    hist_kernel<<<edgeBlocks, 256>>>(ei, deg, E, N);
    scan1_kernel<<<scanBlocks, 1024>>>(deg, off, bsum, N);
    scan3_kernel<<<scanBlocks, 1024>>>(off, cur, bsum, N);
    place_kernel<<<edgeBlocks, 256>>>(ei, cur, csr, E, N);

    // ---- Layer 1 ----
    gather64_kernel<<<gatherBlocks, 256>>>(off, deg, csr, fH, fL, agH, agL, N);
    combine_kernel<128><<<nodeBlocks, 256, SM_GEMM>>>(fH, fL, agH, agL, wp, b1, h1H, h1L, N);
    // ---- Layer 2 ----
    gather128_kernel<<<gatherBlocks, 256>>>(off, deg, csr, h1H, h1L, agH, agL, N);
    combine_kernel<256><<<nodeBlocks, 256, SM_GEMM>>>(h1H, h1L, agH, agL, wp + 16384, b2, h2H, h2L, N);
    // ---- MLP (fused) ----
    mlp_fused_kernel<<<nodeBlocks, 256, SM_GEMM>>>(h2H, h2L, wp + 49152, bm1,
                                                   wp + 81920, bm2, out, N);
}

// round 16
// speedup vs baseline: 1.0527x; 1.0527x over previous
#include <cuda_runtime.h>
#include <math.h>
#include <stdint.h>

#define NN 100000
#define EE 1600000
#define XW 36     // Xr tile row stride (words): (4*ar+ac)%32 conflict-free
#define FB 8704   // words per buffer: Wpack(4096) + Xr(128*36=4608)
#define OF_XR 4096
#define SMF_TOTAL (2 * FB)   // 17,408 words = 69,632 B -> 2 blocks/SM
#define SP 68     // staging plane row stride (words): conflict-free

// -------- scratch (device globals; no allocation allowed) --------
// GEMM X operands in split planes: word = bf16x2 of (k_even, k_odd); hi & lo.
__device__ uint32_t g_fH[(size_t)NN * 32],  g_fL[(size_t)NN * 32];    // feat
__device__ uint32_t g_h1H[(size_t)NN * 64], g_h1L[(size_t)NN * 64];
__device__ uint32_t g_h2H[(size_t)NN * 64], g_h2L[(size_t)NN * 64];
__device__ uint32_t g_agH[(size_t)NN * 64], g_agL[(size_t)NN * 64];
__device__ float    g_h1f[(size_t)NN * 128];   // fp32 h1 for gather128's reads
__device__ float g_wp[92160];   // frag-major packed bf16 hi/lo of [W1|W2|Wm1|Wm2]
__device__ int   g_deg[NN];
__device__ int   g_off[NN];
__device__ int   g_cur[NN];
__device__ int   g_csr[EE];
__device__ int   g_bsum[512];

// -------- helpers --------
__device__ __forceinline__ float sigmoidf_(float x) {
    return 1.0f / (1.0f + __expf(-x));
}
// split float2 into packed bf16x2 hi + bf16x2 lo (element0 -> lower half)
__device__ __forceinline__ void split2(float2 v, uint32_t& hp, uint32_t& lp) {
    asm("cvt.rn.bf16x2.f32 %0, %1, %2;" : "=r"(hp) : "f"(v.y), "f"(v.x));
    float hx = __uint_as_float(hp << 16);
    float hy = __uint_as_float(hp & 0xffff0000u);
    float lx = v.x - hx, ly = v.y - hy;
    asm("cvt.rn.bf16x2.f32 %0, %1, %2;" : "=r"(lp) : "f"(ly), "f"(lx));
}
// decode word -> (even, odd) floats
__device__ __forceinline__ float2 dec2(uint32_t w) {
    return make_float2(__uint_as_float(w << 16), __uint_as_float(w & 0xffff0000u));
}
// D += A(16x16 bf16) * B(16x8 bf16), fp32 accumulate
__device__ __forceinline__ void mma_bf16(float4& d, const uint32_t* a, uint32_t b0, uint32_t b1) {
    asm("mma.sync.aligned.m16n8k16.row.col.f32.bf16.bf16.f32 "
        "{%0,%1,%2,%3}, {%4,%5,%6,%7}, {%8,%9}, {%0,%1,%2,%3};"
        : "+f"(d.x), "+f"(d.y), "+f"(d.z), "+f"(d.w)
        : "r"(a[0]), "r"(a[1]), "r"(a[2]), "r"(a[3]), "r"(b0), "r"(b1));
}
__device__ __forceinline__ void cpasync16(uint32_t dst, const void* src, int srcsize) {
    asm volatile("cp.async.ca.shared.global [%0], [%1], 16, %2;"
                 :: "r"(dst), "l"(src), "r"(srcsize) : "memory");
}
#define CP_COMMIT() asm volatile("cp.async.commit_group;" ::: "memory")
#define CP_WAIT1()  asm volatile("cp.async.wait_group 1;" ::: "memory")

// ============================================================================
// prep: zero deg, split feat into planes, pack weights frag-major (bf16 hi/lo)
// wp: W1 f4 [0,4096); W2 [4096,12288); Wm1 [12288,20480); Wm2 [20480,23040)
// ============================================================================
__global__ void prep1_kernel(int* __restrict__ deg, int n,
                             const float* __restrict__ feat,
                             uint32_t* __restrict__ fH, uint32_t* __restrict__ fL,
                             const float* __restrict__ W1,
                             const float* __restrict__ W2,
                             const float* __restrict__ Wm1,
                             const float* __restrict__ Wm2,
                             float* __restrict__ wp)
{
    int idx = blockIdx.x * blockDim.x + threadIdx.x;
    int stride = gridDim.x * blockDim.x;
    for (int i = idx; i < n; i += stride) deg[i] = 0;
    int nw = n * 32;
    for (int i = idx; i < nw; i += stride) {
        int node = i >> 5, w = i & 31;
        float2 v = *(const float2*)(feat + (size_t)node * 64 + 2 * w);
        uint32_t hp, lp;
        split2(v, hp, lp);
        fH[i] = hp; fL[i] = lp;
    }
    float4* wp4 = (float4*)wp;
    for (int i = idx; i < 23040; i += stride) {
        const float* W; int rs, k0, j;
        if (i < 20480) {
            int jb = 0, local;
            if (i < 4096)        { local = i;          W = W1;  rs = 128; }
            else if (i < 12288)  { local = i - 4096;   W = W2;  rs = 128; }
            else                 { local = i - 12288;  jb = local >> 12; local &= 4095; W = Wm1; rs = 256; }
            int c   = local >> 10;
            int s   = (local >> 9) & 1;
            int wn2 = (local >> 8) & 1;
            int nt  = (local >> 5) & 7;
            int l   = local & 31;
            k0 = c * 32 + s * 16 + 2 * (l & 3);
            j  = jb * 128 + wn2 * 64 + nt * 8 + (l >> 2);
        } else {
            int local = i - 20480;          // [sg(16)][nt(5)][lane(32)]
            int sg  = local / 160;
            int rem = local - sg * 160;
            int nt  = rem >> 5;
            int l   = rem & 31;
            W = Wm2; rs = 40;
            k0 = sg * 16 + 2 * (l & 3);
            j  = nt * 8 + (l >> 2);
        }
        float v00 = W[(size_t)k0 * rs + j];
        float v01 = W[(size_t)(k0 + 1) * rs + j];
        float v10 = W[(size_t)(k0 + 8) * rs + j];
        float v11 = W[(size_t)(k0 + 9) * rs + j];
        uint32_t w0, w2, w1, w3;
        split2(make_float2(v00, v01), w0, w2);
        split2(make_float2(v10, v11), w1, w3);
        wp4[i] = make_float4(__uint_as_float(w0), __uint_as_float(w1),
                             __uint_as_float(w2), __uint_as_float(w3));
    }
}

// -------- CSR build: histogram over dst --------
__global__ void hist_kernel(const int* __restrict__ ei, int* __restrict__ deg,
                            int E, int nNodes) {
    int e = blockIdx.x * blockDim.x + threadIdx.x;
    if (e >= E) return;
    int d = ei[E + e];
    if ((unsigned)d < (unsigned)nNodes) atomicAdd(&deg[d], 1);
}

// -------- scan phase 1: per-block inclusive scan; bsum = raw block totals ----
__global__ void scan1_kernel(const int* __restrict__ deg, int* __restrict__ off,
                             int* __restrict__ bsum, int n) {
    __shared__ int sh[1024];
    int tid = threadIdx.x;
    int i = blockIdx.x * 1024 + tid;
    int v = (i < n) ? deg[i] : 0;
    sh[tid] = v;
    __syncthreads();
    #pragma unroll
    for (int d = 1; d < 1024; d <<= 1) {
        int t = (tid >= d) ? sh[tid - d] : 0;
        __syncthreads();
        sh[tid] += t;
        __syncthreads();
    }
    if (i < n) off[i] = sh[tid] - v;
    if (tid == 1023) bsum[blockIdx.x] = sh[1023];
}

// -------- scan phase 2+3 fused: block computes its own bsum prefix ----------
__global__ void scan3_kernel(int* __restrict__ off, int* __restrict__ cur,
                             const int* __restrict__ bsum, int n) {
    __shared__ int red[32];
    __shared__ int sAdd;
    int tid = threadIdx.x;
    int acc = (tid < blockIdx.x) ? bsum[tid] : 0;   // nb <= 1024
    #pragma unroll
    for (int o = 16; o; o >>= 1) acc += __shfl_down_sync(~0u, acc, o);
    if ((tid & 31) == 0) red[tid >> 5] = acc;
    __syncthreads();
    if (tid == 0) {
        int s = 0;
        #pragma unroll
        for (int w = 0; w < 32; ++w) s += red[w];
        sAdd = s;
    }
    __syncthreads();
    int i = blockIdx.x * 1024 + tid;
    if (i < n) {
        int o = off[i] + sAdd;
        off[i] = o;
        cur[i] = o;
    }
}

// -------- CSR placement --------
__global__ void place_kernel(const int* __restrict__ ei, int* __restrict__ cur,
                             int* __restrict__ csr, int E, int nNodes) {
    int e = blockIdx.x * blockDim.x + threadIdx.x;
    if (e >= E) return;
    int s = ei[e];
    int d = ei[E + e];
    if ((unsigned)s >= (unsigned)nNodes || (unsigned)d >= (unsigned)nNodes) return;
    int pos = atomicAdd(&cur[d], 1);
    csr[pos] = s;
}

// -------- gather64: fp32 feat in (R14 loop), split planes out --------
__global__ void __launch_bounds__(256) gather64_kernel(
    const int* __restrict__ off, const int* __restrict__ deg,
    const int* __restrict__ csr, const float* __restrict__ x,
    uint32_t* __restrict__ aH, uint32_t* __restrict__ aL, int nNodes)
{
    int node = blockIdx.x * 8 + (threadIdx.x >> 5);
    if (node >= nNodes) return;
    int lane = threadIdx.x & 31;
    int beg = off[node], dg = deg[node];
    float2 acc = make_float2(0.f, 0.f);
    for (int e = beg; e < beg + dg; ++e) {
        int s = csr[e];
        float2 v = *(const float2*)(x + (size_t)s * 64 + lane * 2);
        acc.x += v.x; acc.y += v.y;
    }
    float sc = 1.0f / (float)max(dg, 1);
    acc.x *= sc; acc.y *= sc;
    uint32_t hp, lp;
    split2(acc, hp, lp);
    aH[(size_t)node * 32 + lane] = hp;
    aL[(size_t)node * 32 + lane] = lp;
}

// -------- gather128: fp32 h1 in (R14 loop, LDG.128), split planes out --------
// lane covers k = 4*lane..4*lane+3 -> plane words 2*lane, 2*lane+1
__global__ void __launch_bounds__(256) gather128_kernel(
    const int* __restrict__ off, const int* __restrict__ deg,
    const int* __restrict__ csr, const float* __restrict__ x,
    uint32_t* __restrict__ aH, uint32_t* __restrict__ aL, int nNodes)
{
    int node = blockIdx.x * 8 + (threadIdx.x >> 5);
    if (node >= nNodes) return;
    int lane = threadIdx.x & 31;
    int beg = off[node], dg = deg[node];
    float4 acc = make_float4(0.f, 0.f, 0.f, 0.f);
    for (int e = beg; e < beg + dg; ++e) {
        int s = csr[e];
        float4 v = *(const float4*)(x + (size_t)s * 128 + lane * 4);
        acc.x += v.x; acc.y += v.y; acc.z += v.z; acc.w += v.w;
    }
    float sc = 1.0f / (float)max(dg, 1);
    acc.x *= sc; acc.y *= sc; acc.z *= sc; acc.w *= sc;
    uint32_t h0, l0, h1, l1;
    split2(make_float2(acc.x, acc.y), h0, l0);
    split2(make_float2(acc.z, acc.w), h1, l1);
    *(uint2*)(aH + (size_t)node * 64 + 2 * lane) = make_uint2(h0, h1);
    *(uint2*)(aL + (size_t)node * 64 + 2 * lane) = make_uint2(l0, l1);
}

// ============================================================================
// GEMM mainloop body: one 32-k chunk (2 k16-steps) from buffer {Wpack, Xw}.
// A-feed: 16 scalar LDS of pre-split words per step — ZERO cvt in mainloop.
// ============================================================================
__device__ __forceinline__ void mma_chunk(
    const float* Wp, const uint32_t* Xw,
    int wm, int wn2, int lane, float4 C0[8], float4 C1[8])
{
    const int ar = lane >> 2, ac = lane & 3;
    #pragma unroll
    for (int s = 0; s < 2; ++s) {
        uint32_t Ah[2][4], Al[2][4];
        #pragma unroll
        for (int mt = 0; mt < 2; ++mt) {
            int nb = wm + mt * 16 + ar;
            const uint32_t* xp = Xw + nb * XW + s * 8 + ac;
            const uint32_t* xq = xp + 8 * XW;
            Ah[mt][0] = xp[0];  Ah[mt][1] = xq[0];
            Ah[mt][2] = xp[4];  Ah[mt][3] = xq[4];
            Al[mt][0] = xp[16]; Al[mt][1] = xq[16];
            Al[mt][2] = xp[20]; Al[mt][3] = xq[20];
        }
        const float4* bp = (const float4*)Wp + ((s * 2 + wn2) * 8) * 32 + lane;
        #pragma unroll
        for (int nt = 0; nt < 8; ++nt) {
            float4 bw = bp[nt * 32];
            uint32_t bh0 = __float_as_uint(bw.x), bh1 = __float_as_uint(bw.y);
            uint32_t bl0 = __float_as_uint(bw.z), bl1 = __float_as_uint(bw.w);
            mma_bf16(C0[nt], Ah[0], bh0, bh1);
            mma_bf16(C1[nt], Ah[1], bh0, bh1);
            mma_bf16(C0[nt], Al[0], bh0, bh1);
            mma_bf16(C1[nt], Al[1], bh0, bh1);
            mma_bf16(C0[nt], Ah[0], bl0, bl1);
            mma_bf16(C1[nt], Ah[1], bl0, bl1);
        }
    }
}

// ============================================================================
// combine: planes in; planes out (+ optional fp32 out for gather consumption)
// ============================================================================
template<int K>
__global__ void __launch_bounds__(256, 2) combine_kernel(
    const uint32_t* __restrict__ selfH, const uint32_t* __restrict__ selfL,
    const uint32_t* __restrict__ aggH,  const uint32_t* __restrict__ aggL,
    const float* __restrict__ wpG, const float* __restrict__ b,
    uint32_t* __restrict__ outH, uint32_t* __restrict__ outL,
    float* __restrict__ outF, int nNodes)
{
    constexpr int NCH = K / 32;
    constexpr int ROWW = K / 4;
    extern __shared__ float smf[];
    const uint32_t smBase = (uint32_t)__cvta_generic_to_shared(smf);

    const int t = threadIdx.x;
    const int lane = t & 31, warp = t >> 5;
    const int wm = (warp & 3) * 32;
    const int wn2 = warp >> 2;
    const int wn = wn2 * 64;
    const int base = blockIdx.x * 128;
    const int ar = lane >> 2, ac = lane & 3;

    float4 C0[8], C1[8];
    #pragma unroll
    for (int nt = 0; nt < 8; ++nt) {
        int j = wn + nt * 8 + 2 * ac;
        float bx = b[j], by = b[j + 1];
        C0[nt] = make_float4(bx, by, bx, by);
        C1[nt] = make_float4(bx, by, bx, by);
    }

    auto prefetch = [&](int ch, int buf) {
        const uint32_t bb = smBase + (uint32_t)(buf * FB) * 4;
        int g = t & 7;
        bool isAgg = (ch >= NCH / 2);
        int w0 = (isAgg ? ch - NCH / 2 : ch) * 16;
        const uint32_t* pl = (g < 4) ? (isAgg ? aggH : selfH) : (isAgg ? aggL : selfL);
        int gw = (g & 3) * 4;
        const uint32_t* src0 = pl + w0 + gw;
        int col = (g < 4) ? gw : 16 + gw;
        #pragma unroll
        for (int it = 0; it < 4; ++it) {
            int n = (t >> 3) + 32 * it;
            int ngl = base + n;
            int sz = (ngl < nNodes) ? 16 : 0;
            cpasync16(bb + (uint32_t)(OF_XR + n * XW + col) * 4,
                      src0 + (size_t)ngl * ROWW, sz);
        }
        const float* wsrc = wpG + (size_t)ch * 4096;
        #pragma unroll
        for (int r = 0; r < 4; ++r) {
            int i = t + 256 * r;
            cpasync16(bb + (uint32_t)(i * 4) * 4, wsrc + i * 4, 16);
        }
    };

    prefetch(0, 0); CP_COMMIT();

    for (int ch = 0; ch < NCH; ++ch) {
        __syncthreads();
        if (ch + 1 < NCH) prefetch(ch + 1, (ch + 1) & 1);
        CP_COMMIT();
        CP_WAIT1();
        __syncthreads();
        const float* bufp = smf + (ch & 1) * FB;
        mma_chunk(bufp, (const uint32_t*)(bufp + OF_XR), wm, wn2, lane, C0, C1);
    }
    __syncthreads();   // buffers free; reuse smem as split staging planes

    uint32_t* Rsh = (uint32_t*)smf;        // [128][SP]
    uint32_t* Rsl = Rsh + 128 * SP;        // [128][SP]
    #pragma unroll
    for (int mt = 0; mt < 2; ++mt) {
        int row = wm + mt * 16 + ar;
        float4* Cm = (mt == 0) ? C0 : C1;
        #pragma unroll
        for (int nt = 0; nt < 8; ++nt) {
            int colw = (wn >> 1) + nt * 4 + ac;
            float4 c = Cm[nt];
            uint32_t hp, lp;
            split2(make_float2(sigmoidf_(c.x), sigmoidf_(c.y)), hp, lp);
            Rsh[row * SP + colw] = hp; Rsl[row * SP + colw] = lp;
            split2(make_float2(sigmoidf_(c.z), sigmoidf_(c.w)), hp, lp);
            Rsh[(row + 8) * SP + colw] = hp; Rsl[(row + 8) * SP + colw] = lp;
        }
    }
    __syncthreads();

    if (base + 128 <= nNodes) {
        for (int i = t; i < 128 * 16; i += 256) {
            int n = i >> 4, q = (i & 15) * 4;
            float4 h4 = *(const float4*)(Rsh + n * SP + q);
            float4 l4 = *(const float4*)(Rsl + n * SP + q);
            *(float4*)(outH + (size_t)(base + n) * 64 + q) = h4;
            *(float4*)(outL + (size_t)(base + n) * 64 + q) = l4;
            if (outF) {
                float2 a0 = dec2(__float_as_uint(h4.x)), d0 = dec2(__float_as_uint(l4.x));
                float2 a1 = dec2(__float_as_uint(h4.y)), d1 = dec2(__float_as_uint(l4.y));
                float2 a2 = dec2(__float_as_uint(h4.z)), d2 = dec2(__float_as_uint(l4.z));
                float2 a3 = dec2(__float_as_uint(h4.w)), d3 = dec2(__float_as_uint(l4.w));
                float4 f0 = make_float4(a0.x + d0.x, a0.y + d0.y, a1.x + d1.x, a1.y + d1.y);
                float4 f1 = make_float4(a2.x + d2.x, a2.y + d2.y, a3.x + d3.x, a3.y + d3.y);
                float* fo = outF + (size_t)(base + n) * 128 + 2 * q;
                *(float4*)fo = f0;
                *(float4*)(fo + 4) = f1;
            }
        }
    } else {
        for (int i = t; i < 128 * 64; i += 256) {
            int n = i >> 6, w = i & 63;
            if (base + n < nNodes) {
                uint32_t hp = Rsh[n * SP + w], lp = Rsl[n * SP + w];
                outH[(size_t)(base + n) * 64 + w] = hp;
                outL[(size_t)(base + n) * 64 + w] = lp;
                if (outF) {
                    float2 a = dec2(hp), d = dec2(lp);
                    *(float2*)(outF + (size_t)(base + n) * 128 + 2 * w)
                        = make_float2(a.x + d.x, a.y + d.y);
                }
            }
        }
    }
}

// ============================================================================
// mlp fused: out = relu(h2 @ Wm1 + bm1) @ Wm2 + bm2   (h2 in split planes)
// ============================================================================
__global__ void __launch_bounds__(256, 2) mlp_fused_kernel(
    const uint32_t* __restrict__ h2H, const uint32_t* __restrict__ h2L,
    const float* __restrict__ wpG,    // packed Wm1 (2 jb blobs of 16384 floats)
    const float* __restrict__ bm1,    // [256]
    const float* __restrict__ wp2G,   // packed Wm2 [16 sg][5 nt][32 lane] float4
    const float* __restrict__ bm2,    // [40]
    float* __restrict__ out,          // [N, 40]
    int nNodes)
{
    extern __shared__ float smf[];
    const uint32_t smBase = (uint32_t)__cvta_generic_to_shared(smf);

    const int t = threadIdx.x;
    const int lane = t & 31, warp = t >> 5;
    const int wm = (warp & 3) * 32;
    const int wn2 = warp >> 2;
    const int wn = wn2 * 64;
    const int base = blockIdx.x * 128;
    const int ar = lane >> 2, ac = lane & 3;

    auto prefetch = [&](int pass, int ch, int buf) {
        const uint32_t bb = smBase + (uint32_t)(buf * FB) * 4;
        int g = t & 7;
        int w0 = ch * 16;
        const uint32_t* pl = (g < 4) ? h2H : h2L;
        int gw = (g & 3) * 4;
        const uint32_t* src0 = pl + w0 + gw;
        int col = (g < 4) ? gw : 16 + gw;
        #pragma unroll
        for (int it = 0; it < 4; ++it) {
            int n = (t >> 3) + 32 * it;
            int ngl = base + n;
            int sz = (ngl < nNodes) ? 16 : 0;
            cpasync16(bb + (uint32_t)(OF_XR + n * XW + col) * 4,
                      src0 + (size_t)ngl * 64, sz);
        }
        const float* wsrc = wpG + (size_t)pass * 16384 + (size_t)ch * 4096;
        #pragma unroll
        for (int r = 0; r < 4; ++r) {
            int i = t + 256 * r;
            cpasync16(bb + (uint32_t)(i * 4) * 4, wsrc + i * 4, 16);
        }
    };

    // persistent output accumulators: 16 nodes x 40 outs per warp
    float4 O[5];
    #pragma unroll
    for (int nt = 0; nt < 5; ++nt) {
        int j = nt * 8 + 2 * ac;
        float bx = bm2[j], by = bm2[j + 1];
        O[nt] = make_float4(bx, by, bx, by);
    }

    for (int pass = 0; pass < 2; ++pass) {
        float4 C0[8], C1[8];
        #pragma unroll
        for (int nt = 0; nt < 8; ++nt) {
            int j = pass * 128 + wn + nt * 8 + 2 * ac;
            float bx = bm1[j], by = bm1[j + 1];
            C0[nt] = make_float4(bx, by, bx, by);
            C1[nt] = make_float4(bx, by, bx, by);
        }

        prefetch(pass, 0, 0); CP_COMMIT();
        for (int ch = 0; ch < 4; ++ch) {
            __syncthreads();
            if (ch + 1 < 4) prefetch(pass, ch + 1, (ch + 1) & 1);
            CP_COMMIT();
            CP_WAIT1();
            __syncthreads();
            const float* bufp = smf + (ch & 1) * FB;
            mma_chunk(bufp, (const uint32_t*)(bufp + OF_XR), wm, wn2, lane, C0, C1);
        }
        __syncthreads();   // pipeline drained; stage hidden as split planes

        uint32_t* Rsh = (uint32_t*)smf;    // [128 node][SP] node-major
        uint32_t* Rsl = Rsh + 128 * SP;
        #pragma unroll
        for (int mt = 0; mt < 2; ++mt) {
            int row = wm + mt * 16 + ar;
            float4* Cm = (mt == 0) ? C0 : C1;
            #pragma unroll
            for (int nt = 0; nt < 8; ++nt) {
                int colw = (wn >> 1) + nt * 4 + ac;
                float4 c = Cm[nt];
                uint32_t hp, lp;
                split2(make_float2(fmaxf(c.x, 0.f), fmaxf(c.y, 0.f)), hp, lp);
                Rsh[row * SP + colw] = hp; Rsl[row * SP + colw] = lp;
                split2(make_float2(fmaxf(c.z, 0.f), fmaxf(c.w, 0.f)), hp, lp);
                Rsh[(row + 8) * SP + colw] = hp; Rsl[(row + 8) * SP + colw] = lp;
            }
        }
        __syncthreads();

        // ---- second GEMM: O += hidden(this pass's 128 k) @ Wm2 ----
        {
            const int n0 = warp * 16 + ar;
            const float4* wp2f = (const float4*)wp2G;
            #pragma unroll
            for (int s8 = 0; s8 < 8; ++s8) {
                const uint32_t* xp = Rsh + n0 * SP + s8 * 8 + ac;
                const uint32_t* xq = xp + 8 * SP;
                const uint32_t* yp = Rsl + n0 * SP + s8 * 8 + ac;
                const uint32_t* yq = yp + 8 * SP;
                uint32_t Ah[4] = { xp[0], xq[0], xp[4], xq[4] };
                uint32_t Al[4] = { yp[0], yq[0], yp[4], yq[4] };
                const int sg = pass * 8 + s8;
                #pragma unroll
                for (int nt = 0; nt < 5; ++nt) {
                    float4 bw = __ldg(wp2f + (sg * 5 + nt) * 32 + lane);
                    uint32_t bh0 = __float_as_uint(bw.x), bh1 = __float_as_uint(bw.y);
                    uint32_t bl0 = __float_as_uint(bw.z), bl1 = __float_as_uint(bw.w);
                    mma_bf16(O[nt], Ah, bh0, bh1);
                    mma_bf16(O[nt], Al, bh0, bh1);
                    mma_bf16(O[nt], Ah, bl0, bl1);
                }
            }
        }
        __syncthreads();   // stage-2 reads done before next pass's prefetch
    }

    // ---- final epilogue: stage O [128 node][44], coalesced write ----
    float* Os = smf;
    {
        const int n0 = warp * 16 + ar;
        #pragma unroll
        for (int nt = 0; nt < 5; ++nt) {
            int col = nt * 8 + 2 * ac;
            *(float2*)(Os + n0 * 44 + col)       = make_float2(O[nt].x, O[nt].y);
            *(float2*)(Os + (n0 + 8) * 44 + col) = make_float2(O[nt].z, O[nt].w);
        }
    }
    __syncthreads();

    const float4* Os4 = (const float4*)Os;
    float4* out4 = (float4*)out;
    for (int i = t; i < 128 * 10; i += 256) {
        int n = i / 10, q = i - n * 10;
        int ngl = base + n;
        if (ngl < nNodes) out4[(size_t)ngl * 10 + q] = Os4[n * 11 + q];
    }
}

// -------- launch --------
extern "C" void kernel_launch(void* const* d_in, const int* in_sizes, int n_in,
                              void* d_out, int out_size)
{
    const float* feat = (const float*)d_in[0];
    const int*   ei   = (const int*)d_in[1];     // int32 (JAX x64 disabled)
    const float* W1  = (const float*)d_in[2];
    const float* b1  = (const float*)d_in[3];
    const float* W2  = (const float*)d_in[4];
    const float* b2  = (const float*)d_in[5];
    const float* Wm1 = (const float*)d_in[6];
    const float* bm1 = (const float*)d_in[7];
    const float* Wm2 = (const float*)d_in[8];
    const float* bm2 = (const float*)d_in[9];
    float* out = (float*)d_out;

    const int N = in_sizes[0] / 64;     // 100000
    const int E = in_sizes[1] / 2;      // 1600000

    uint32_t *fH, *fL, *h1H, *h1L, *h2H, *h2L, *agH, *agL;
    float *wp, *h1f;
    int *deg, *off, *cur, *csr, *bsum;
    cudaGetSymbolAddress((void**)&fH,  g_fH);
    cudaGetSymbolAddress((void**)&fL,  g_fL);
    cudaGetSymbolAddress((void**)&h1H, g_h1H);
    cudaGetSymbolAddress((void**)&h1L, g_h1L);
    cudaGetSymbolAddress((void**)&h2H, g_h2H);
    cudaGetSymbolAddress((void**)&h2L, g_h2L);
    cudaGetSymbolAddress((void**)&agH, g_agH);
    cudaGetSymbolAddress((void**)&agL, g_agL);
    cudaGetSymbolAddress((void**)&h1f, g_h1f);
    cudaGetSymbolAddress((void**)&wp,  g_wp);
    cudaGetSymbolAddress((void**)&deg, g_deg);
    cudaGetSymbolAddress((void**)&off, g_off);
    cudaGetSymbolAddress((void**)&cur, g_cur);
    cudaGetSymbolAddress((void**)&csr, g_csr);
    cudaGetSymbolAddress((void**)&bsum, g_bsum);

    const int SM_GEMM = SMF_TOTAL * 4;   // 69,632 B -> 2 blocks/SM
    cudaFuncSetAttribute(combine_kernel<128>, cudaFuncAttributeMaxDynamicSharedMemorySize, SM_GEMM);
    cudaFuncSetAttribute(combine_kernel<256>, cudaFuncAttributeMaxDynamicSharedMemorySize, SM_GEMM);
    cudaFuncSetAttribute(mlp_fused_kernel,    cudaFuncAttributeMaxDynamicSharedMemorySize, SM_GEMM);

    const int nodeBlocks = (N + 127) / 128;      // 782
    const int gatherBlocks = (N + 7) / 8;        // 12500
    const int scanBlocks = (N + 1023) / 1024;    // 98
    const int edgeBlocks = (E + 255) / 256;

    // ---- prep (deg zero + feat split + W pack) & CSR build ----
    prep1_kernel<<<2048, 256>>>(deg, N, feat, fH, fL, W1, W2, Wm1, Wm2, wp);
    hist_kernel<<<edgeBlocks, 256>>>(ei, deg, E, N);
    scan1_kernel<<<scanBlocks, 1024>>>(deg, off, bsum, N);
    scan3_kernel<<<scanBlocks, 1024>>>(off, cur, bsum, N);
    place_kernel<<<edgeBlocks, 256>>>(ei, cur, csr, E, N);

    // ---- Layer 1: gather reads fp32 feat; combine emits h1 planes + fp32 ----
    gather64_kernel<<<gatherBlocks, 256>>>(off, deg, csr, feat, agH, agL, N);
    combine_kernel<128><<<nodeBlocks, 256, SM_GEMM>>>(fH, fL, agH, agL, wp, b1,
                                                      h1H, h1L, h1f, N);
    // ---- Layer 2: gather reads fp32 h1; combine emits h2 planes only ----
    gather128_kernel<<<gatherBlocks, 256>>>(off, deg, csr, h1f, agH, agL, N);
    combine_kernel<256><<<nodeBlocks, 256, SM_GEMM>>>(h1H, h1L, agH, agL, wp + 16384, b2,
                                                      h2H, h2L, (float*)0, N);
    // ---- MLP (fused) ----
    mlp_fused_kernel<<<nodeBlocks, 256, SM_GEMM>>>(h2H, h2L, wp + 49152, bm1,
                                                   wp + 81920, bm2, out, N);
}

// round 17
// speedup vs baseline: 1.1575x; 1.0995x over previous
#include <cuda_runtime.h>
#include <math.h>
#include <stdint.h>

#define NN 100000
#define EE 1600000
#define XRS 40    // raw X tile row stride (floats): LDS.64 at exact 2-phase floor
#define FB 9216   // floats per buffer: Wpack(4096) + Xr(5120)
#define OF_XR 4096
#define SMF_TOTAL (2 * FB)   // 18,432 floats = 73,728 B -> 2 blocks/SM

// -------- scratch (device globals; no allocation allowed) --------
__device__ float g_agg[(size_t)NN * 128];
__device__ float g_h1[(size_t)NN * 128];
__device__ float g_h2[(size_t)NN * 128];
__device__ float g_wp[92160];   // frag-major packed bf16 hi/lo of [W1|W2|Wm1|Wm2]
__device__ int   g_deg[NN];
__device__ int   g_off[NN];
__device__ int   g_cur[NN];
__device__ int   g_csr[EE];
__device__ int   g_bsum[512];

// -------- helpers --------
__device__ __forceinline__ float sigmoidf_(float x) {
    return 1.0f / (1.0f + __expf(-x));
}
// split float2 into packed bf16x2 hi + bf16x2 lo (element0 -> lower half)
__device__ __forceinline__ void split2(float2 v, uint32_t& hp, uint32_t& lp) {
    asm("cvt.rn.bf16x2.f32 %0, %1, %2;" : "=r"(hp) : "f"(v.y), "f"(v.x));
    float hx = __uint_as_float(hp << 16);
    float hy = __uint_as_float(hp & 0xffff0000u);
    float lx = v.x - hx, ly = v.y - hy;
    asm("cvt.rn.bf16x2.f32 %0, %1, %2;" : "=r"(lp) : "f"(ly), "f"(lx));
}
// D += A(16x16 bf16) * B(16x8 bf16), fp32 accumulate
__device__ __forceinline__ void mma_bf16(float4& d, const uint32_t* a, uint32_t b0, uint32_t b1) {
    asm("mma.sync.aligned.m16n8k16.row.col.f32.bf16.bf16.f32 "
        "{%0,%1,%2,%3}, {%4,%5,%6,%7}, {%8,%9}, {%0,%1,%2,%3};"
        : "+f"(d.x), "+f"(d.y), "+f"(d.z), "+f"(d.w)
        : "r"(a[0]), "r"(a[1]), "r"(a[2]), "r"(a[3]), "r"(b0), "r"(b1));
}
__device__ __forceinline__ void cpasync16(uint32_t dst, const void* src, int srcsize) {
    asm volatile("cp.async.ca.shared.global [%0], [%1], 16, %2;"
                 :: "r"(dst), "l"(src), "r"(srcsize) : "memory");
}
#define CP_COMMIT() asm volatile("cp.async.commit_group;" ::: "memory")
#define CP_WAIT1()  asm volatile("cp.async.wait_group 1;" ::: "memory")

// ============================================================================
// prep: zero deg AND pack weights frag-major (bf16 hi/lo, mma-lane layout):
// per 128-j block: [chunk c(32k)][s(2 k16)][wn2(2)][nt(8)][lane(32)]
//   x float4 {Bh0, Bh1, Bl0, Bl1}
// W1: f4 units [0,4096); W2: [4096,12288); Wm1: [12288,20480); Wm2: [20480,23040)
// Wm2 pack layout: [sg(16 k16-steps)][nt(5)][lane(32)]
// ============================================================================
__global__ void prep1_kernel(int* __restrict__ deg, int n,
                             const float* __restrict__ W1,
                             const float* __restrict__ W2,
                             const float* __restrict__ Wm1,
                             const float* __restrict__ Wm2,
                             float* __restrict__ wp)
{
    int idx = blockIdx.x * blockDim.x + threadIdx.x;
    int stride = gridDim.x * blockDim.x;
    for (int i = idx; i < n; i += stride) deg[i] = 0;
    float4* wp4 = (float4*)wp;
    for (int i = idx; i < 23040; i += stride) {
        const float* W; int rs, k0, j;
        if (i < 20480) {
            int jb = 0, local;
            if (i < 4096)        { local = i;          W = W1;  rs = 128; }
            else if (i < 12288)  { local = i - 4096;   W = W2;  rs = 128; }
            else                 { local = i - 12288;  jb = local >> 12; local &= 4095; W = Wm1; rs = 256; }
            int c   = local >> 10;
            int s   = (local >> 9) & 1;
            int wn2 = (local >> 8) & 1;
            int nt  = (local >> 5) & 7;
            int l   = local & 31;
            k0 = c * 32 + s * 16 + 2 * (l & 3);
            j  = jb * 128 + wn2 * 64 + nt * 8 + (l >> 2);
        } else {
            int local = i - 20480;          // [sg(16)][nt(5)][lane(32)]
            int sg  = local / 160;
            int rem = local - sg * 160;
            int nt  = rem >> 5;
            int l   = rem & 31;
            W = Wm2; rs = 40;
            k0 = sg * 16 + 2 * (l & 3);
            j  = nt * 8 + (l >> 2);
        }
        float v00 = W[(size_t)k0 * rs + j];
        float v01 = W[(size_t)(k0 + 1) * rs + j];
        float v10 = W[(size_t)(k0 + 8) * rs + j];
        float v11 = W[(size_t)(k0 + 9) * rs + j];
        uint32_t w0, w2, w1, w3;
        split2(make_float2(v00, v01), w0, w2);
        split2(make_float2(v10, v11), w1, w3);
        wp4[i] = make_float4(__uint_as_float(w0), __uint_as_float(w1),
                             __uint_as_float(w2), __uint_as_float(w3));
    }
}

// -------- CSR build: histogram over dst --------
__global__ void hist_kernel(const int* __restrict__ ei, int* __restrict__ deg,
                            int E, int nNodes) {
    int e = blockIdx.x * blockDim.x + threadIdx.x;
    if (e >= E) return;
    int d = ei[E + e];
    if ((unsigned)d < (unsigned)nNodes) atomicAdd(&deg[d], 1);
}

// -------- scan phase 1: per-block inclusive scan; bsum = raw block totals ----
__global__ void scan1_kernel(const int* __restrict__ deg, int* __restrict__ off,
                             int* __restrict__ bsum, int n) {
    __shared__ int sh[1024];
    int tid = threadIdx.x;
    int i = blockIdx.x * 1024 + tid;
    int v = (i < n) ? deg[i] : 0;
    sh[tid] = v;
    __syncthreads();
    #pragma unroll
    for (int d = 1; d < 1024; d <<= 1) {
        int t = (tid >= d) ? sh[tid - d] : 0;
        __syncthreads();
        sh[tid] += t;
        __syncthreads();
    }
    if (i < n) off[i] = sh[tid] - v;
    if (tid == 1023) bsum[blockIdx.x] = sh[1023];
}

// -------- scan phase 2+3 fused: block computes its own bsum prefix ----------
__global__ void scan3_kernel(int* __restrict__ off, int* __restrict__ cur,
                             const int* __restrict__ bsum, int n) {
    __shared__ int red[32];
    __shared__ int sAdd;
    int tid = threadIdx.x;
    int acc = (tid < blockIdx.x) ? bsum[tid] : 0;   // nb <= 1024
    #pragma unroll
    for (int o = 16; o; o >>= 1) acc += __shfl_down_sync(~0u, acc, o);
    if ((tid & 31) == 0) red[tid >> 5] = acc;
    __syncthreads();
    if (tid == 0) {
        int s = 0;
        #pragma unroll
        for (int w = 0; w < 32; ++w) s += red[w];
        sAdd = s;
    }
    __syncthreads();
    int i = blockIdx.x * 1024 + tid;
    if (i < n) {
        int o = off[i] + sAdd;
        off[i] = o;
        cur[i] = o;
    }
}

// -------- CSR placement --------
__global__ void place_kernel(const int* __restrict__ ei, int* __restrict__ cur,
                             int* __restrict__ csr, int E, int nNodes) {
    int e = blockIdx.x * blockDim.x + threadIdx.x;
    if (e >= E) return;
    int s = ei[e];
    int d = ei[E + e];
    if ((unsigned)s >= (unsigned)nNodes || (unsigned)d >= (unsigned)nNodes) return;
    int pos = atomicAdd(&cur[d], 1);
    csr[pos] = s;
}

// -------- gather aggregate: warp per node --------
__global__ void __launch_bounds__(256) gather64_kernel(
    const int* __restrict__ off, const int* __restrict__ deg,
    const int* __restrict__ csr, const float* __restrict__ x,
    float* __restrict__ agg, int nNodes)
{
    int node = blockIdx.x * 8 + (threadIdx.x >> 5);
    if (node >= nNodes) return;
    int lane = threadIdx.x & 31;
    int beg = off[node], dg = deg[node];
    float2 acc = make_float2(0.f, 0.f);
    for (int e = beg; e < beg + dg; ++e) {
        int s = csr[e];
        float2 v = *(const float2*)(x + (size_t)s * 64 + lane * 2);
        acc.x += v.x; acc.y += v.y;
    }
    float sc = 1.0f / (float)max(dg, 1);
    acc.x *= sc; acc.y *= sc;
    *(float2*)(agg + (size_t)node * 64 + lane * 2) = acc;
}

__global__ void __launch_bounds__(256) gather128_kernel(
    const int* __restrict__ off, const int* __restrict__ deg,
    const int* __restrict__ csr, const float* __restrict__ x,
    float* __restrict__ agg, int nNodes)
{
    int node = blockIdx.x * 8 + (threadIdx.x >> 5);
    if (node >= nNodes) return;
    int lane = threadIdx.x & 31;
    int beg = off[node], dg = deg[node];
    float4 acc = make_float4(0.f, 0.f, 0.f, 0.f);
    for (int e = beg; e < beg + dg; ++e) {
        int s = csr[e];
        float4 v = *(const float4*)(x + (size_t)s * 128 + lane * 4);
        acc.x += v.x; acc.y += v.y; acc.z += v.z; acc.w += v.w;
    }
    float sc = 1.0f / (float)max(dg, 1);
    acc.x *= sc; acc.y *= sc; acc.z *= sc; acc.w *= sc;
    *(float4*)(agg + (size_t)node * 128 + lane * 4) = acc;
}

// ============================================================================
// GEMM mainloop body: one 32-k chunk (2 k16-steps) from buffer {Wpack, Xr}.
// A: 4x LDS.64 raw fp32 + register bf16x2 split. B: 1x LDS.128 frag per nt.
// 48 m16n8k16 bf16 mmas per k16-step (2-term compensated: hh + lh + hl).
// ============================================================================
__device__ __forceinline__ void mma_chunk(
    const float* Wp, const float* Xr,
    int wm, int wn2, int lane, float4 C0[8], float4 C1[8])
{
    const int ar = lane >> 2, ac = lane & 3;
    #pragma unroll
    for (int s = 0; s < 2; ++s) {
        uint32_t Ah[2][4], Al[2][4];
        #pragma unroll
        for (int mt = 0; mt < 2; ++mt) {
            int nb = wm + mt * 16 + ar;
            const float* xp = Xr + nb * XRS + s * 16 + 2 * ac;
            float2 p0 = *(const float2*)(xp);
            float2 p1 = *(const float2*)(xp + 8 * XRS);
            float2 p2 = *(const float2*)(xp + 8);
            float2 p3 = *(const float2*)(xp + 8 * XRS + 8);
            split2(p0, Ah[mt][0], Al[mt][0]);
            split2(p1, Ah[mt][1], Al[mt][1]);
            split2(p2, Ah[mt][2], Al[mt][2]);
            split2(p3, Ah[mt][3], Al[mt][3]);
        }
        const float4* bp = (const float4*)Wp + ((s * 2 + wn2) * 8) * 32 + lane;
        #pragma unroll
        for (int nt = 0; nt < 8; ++nt) {
            float4 bw = bp[nt * 32];
            uint32_t bh0 = __float_as_uint(bw.x), bh1 = __float_as_uint(bw.y);
            uint32_t bl0 = __float_as_uint(bw.z), bl1 = __float_as_uint(bw.w);
            mma_bf16(C0[nt], Ah[0], bh0, bh1);
            mma_bf16(C1[nt], Ah[1], bh0, bh1);
            mma_bf16(C0[nt], Al[0], bh0, bh1);
            mma_bf16(C1[nt], Al[1], bh0, bh1);
            mma_bf16(C0[nt], Ah[0], bl0, bl1);
            mma_bf16(C1[nt], Ah[1], bl0, bl1);
        }
    }
}

// ============================================================================
// combine (bf16 compensated mma, double-buffered cp.async):
// out[128n x 128j] = sigmoid(concat(self, agg) @ W + b)   (agg pre-divided)
// ============================================================================
template<int K>
__global__ void __launch_bounds__(256, 2) combine_kernel(
    const float* __restrict__ self,   // [N, K/2]
    const float* __restrict__ agg,    // [N, K/2]  (already mean)
    const float* __restrict__ wpG,    // packed W (frag-major blobs of 4096 floats/chunk)
    const float* __restrict__ b,      // [128]
    float* __restrict__ out,          // [N, 128]
    int nNodes)
{
    constexpr int SELF = K / 2;
    constexpr int NCH = K / 32;
    extern __shared__ float smf[];
    const uint32_t smBase = (uint32_t)__cvta_generic_to_shared(smf);

    const int t = threadIdx.x;
    const int lane = t & 31, warp = t >> 5;
    const int wm = (warp & 3) * 32;
    const int wn2 = warp >> 2;
    const int wn = wn2 * 64;
    const int base = blockIdx.x * 128;
    const int ar = lane >> 2, ac = lane & 3;

    float4 C0[8], C1[8];
    #pragma unroll
    for (int nt = 0; nt < 8; ++nt) {
        int j = wn + nt * 8 + 2 * ac;
        float bx = b[j], by = b[j + 1];
        C0[nt] = make_float4(bx, by, bx, by);
        C1[nt] = make_float4(bx, by, bx, by);
    }

    auto prefetch = [&](int ch, int buf) {
        const uint32_t bb = smBase + (uint32_t)(buf * FB) * 4;
        int g = t & 7;
        int kg = ch * 32 + g * 4;
        const float* src0 = (kg < SELF) ? (self + kg) : (agg + (kg - SELF));
        #pragma unroll
        for (int it = 0; it < 4; ++it) {
            int n = (t >> 3) + 32 * it;
            int ngl = base + n;
            int sz = (ngl < nNodes) ? 16 : 0;
            cpasync16(bb + (uint32_t)(OF_XR + n * XRS + g * 4) * 4,
                      src0 + (size_t)ngl * SELF, sz);
        }
        const float* wsrc = wpG + (size_t)ch * 4096;
        #pragma unroll
        for (int r = 0; r < 4; ++r) {
            int i = t + 256 * r;
            cpasync16(bb + (uint32_t)(i * 4) * 4, wsrc + i * 4, 16);
        }
    };

    prefetch(0, 0); CP_COMMIT();

    for (int ch = 0; ch < NCH; ++ch) {
        __syncthreads();
        if (ch + 1 < NCH) prefetch(ch + 1, (ch + 1) & 1);
        CP_COMMIT();
        CP_WAIT1();
        __syncthreads();
        const float* bufp = smf + (ch & 1) * FB;
        mma_chunk(bufp, bufp + OF_XR, wm, wn2, lane, C0, C1);
    }
    __syncthreads();   // buffers free; reuse smem as staging

    float* Rs = smf;   // [128 node][132]
    #pragma unroll
    for (int mt = 0; mt < 2; ++mt) {
        int row = wm + mt * 16 + ar;
        float4* Cm = (mt == 0) ? C0 : C1;
        #pragma unroll
        for (int nt = 0; nt < 8; ++nt) {
            int col = wn + nt * 8 + 2 * ac;
            float4 c = Cm[nt];
            *(float2*)(Rs + row * 132 + col)       = make_float2(sigmoidf_(c.x), sigmoidf_(c.y));
            *(float2*)(Rs + (row + 8) * 132 + col) = make_float2(sigmoidf_(c.z), sigmoidf_(c.w));
        }
    }
    __syncthreads();

    const float4* Rs4 = (const float4*)Rs;
    float4* out4 = (float4*)out;
    for (int i = t; i < 128 * 32; i += 256) {
        int n = i >> 5, q = i & 31;
        int ngl = base + n;
        if (ngl < nNodes) out4[(size_t)ngl * 32 + q] = Rs4[n * 33 + q];
    }
}

// ============================================================================
// mlp fused (bf16 compensated mma): out = relu(h2 @ Wm1 + bm1) @ Wm2 + bm2
// Per pass (2 x 128 hidden cols): mainloop -> C, stage relu(C) transposed in
// smem Rs[j][132], then SECOND GEMM accumulates O += split(Rs) @ Wm2pack.
// ============================================================================
__global__ void __launch_bounds__(256, 2) mlp_fused_kernel(
    const float* __restrict__ h2,     // [N, 128]
    const float* __restrict__ wpG,    // packed Wm1 (2 jb blobs of 16384 floats)
    const float* __restrict__ bm1,    // [256]
    const float* __restrict__ wp2G,   // packed Wm2 [16 sg][5 nt][32 lane] float4
    const float* __restrict__ bm2,    // [40]
    float* __restrict__ out,          // [N, 40]
    int nNodes)
{
    extern __shared__ float smf[];
    const uint32_t smBase = (uint32_t)__cvta_generic_to_shared(smf);

    const int t = threadIdx.x;
    const int lane = t & 31, warp = t >> 5;
    const int wm = (warp & 3) * 32;
    const int wn2 = warp >> 2;
    const int wn = wn2 * 64;
    const int base = blockIdx.x * 128;
    const int ar = lane >> 2, ac = lane & 3;

    auto prefetch = [&](int pass, int ch, int buf) {
        const uint32_t bb = smBase + (uint32_t)(buf * FB) * 4;
        int g = t & 7;
        int col = ch * 32 + g * 4;
        #pragma unroll
        for (int it = 0; it < 4; ++it) {
            int n = (t >> 3) + 32 * it;
            int ngl = base + n;
            int sz = (ngl < nNodes) ? 16 : 0;
            cpasync16(bb + (uint32_t)(OF_XR + n * XRS + g * 4) * 4,
                      h2 + (size_t)ngl * 128 + col, sz);
        }
        const float* wsrc = wpG + (size_t)pass * 16384 + (size_t)ch * 4096;
        #pragma unroll
        for (int r = 0; r < 4; ++r) {
            int i = t + 256 * r;
            cpasync16(bb + (uint32_t)(i * 4) * 4, wsrc + i * 4, 16);
        }
    };

    // persistent output accumulators: 16 nodes x 40 outs per warp
    float4 O[5];
    #pragma unroll
    for (int nt = 0; nt < 5; ++nt) {
        int j = nt * 8 + 2 * ac;
        float bx = bm2[j], by = bm2[j + 1];
        O[nt] = make_float4(bx, by, bx, by);
    }

    for (int pass = 0; pass < 2; ++pass) {
        float4 C0[8], C1[8];
        #pragma unroll
        for (int nt = 0; nt < 8; ++nt) {
            int j = pass * 128 + wn + nt * 8 + 2 * ac;
            float bx = bm1[j], by = bm1[j + 1];
            C0[nt] = make_float4(bx, by, bx, by);
            C1[nt] = make_float4(bx, by, bx, by);
        }

        prefetch(pass, 0, 0); CP_COMMIT();
        for (int ch = 0; ch < 4; ++ch) {
            __syncthreads();
            if (ch + 1 < 4) prefetch(pass, ch + 1, (ch + 1) & 1);
            CP_COMMIT();
            CP_WAIT1();
            __syncthreads();
            const float* bufp = smf + (ch & 1) * FB;
            mma_chunk(bufp, bufp + OF_XR, wm, wn2, lane, C0, C1);
        }
        __syncthreads();   // pipeline drained; buffers free for staging

        float* Rs = smf;   // [128 j][132] transposed hidden staging (relu applied)
        #pragma unroll
        for (int mt = 0; mt < 2; ++mt) {
            int row = wm + mt * 16 + ar;   // node
            float4* Cm = (mt == 0) ? C0 : C1;
            #pragma unroll
            for (int nt = 0; nt < 8; ++nt) {
                int col = wn + nt * 8 + 2 * ac;   // j (hidden)
                float4 c = Cm[nt];
                Rs[col * 132 + row]           = fmaxf(c.x, 0.f);
                Rs[(col + 1) * 132 + row]     = fmaxf(c.y, 0.f);
                Rs[col * 132 + row + 8]       = fmaxf(c.z, 0.f);
                Rs[(col + 1) * 132 + row + 8] = fmaxf(c.w, 0.f);
            }
        }
        __syncthreads();

        // ---- second GEMM: O += hm(this pass's 128 k) @ Wm2 ----
        {
            const int n0 = warp * 16 + ar;   // this thread's node rows (and +8)
            const float4* wp2f = (const float4*)wp2G;
            #pragma unroll
            for (int s = 0; s < 8; ++s) {
                const int ko = s * 16 + 2 * ac;
                const float* rp = Rs + n0;
                float2 p0 = make_float2(rp[ko * 132],        rp[(ko + 1) * 132]);
                float2 p1 = make_float2(rp[ko * 132 + 8],    rp[(ko + 1) * 132 + 8]);
                float2 p2 = make_float2(rp[(ko + 8) * 132],  rp[(ko + 9) * 132]);
                float2 p3 = make_float2(rp[(ko + 8) * 132 + 8], rp[(ko + 9) * 132 + 8]);
                uint32_t Ah[4], Al[4];
                split2(p0, Ah[0], Al[0]);
                split2(p1, Ah[1], Al[1]);
                split2(p2, Ah[2], Al[2]);
                split2(p3, Ah[3], Al[3]);
                const int sg = pass * 8 + s;
                #pragma unroll
                for (int nt = 0; nt < 5; ++nt) {
                    float4 bw = __ldg(wp2f + (sg * 5 + nt) * 32 + lane);
                    uint32_t bh0 = __float_as_uint(bw.x), bh1 = __float_as_uint(bw.y);
                    uint32_t bl0 = __float_as_uint(bw.z), bl1 = __float_as_uint(bw.w);
                    mma_bf16(O[nt], Ah, bh0, bh1);
                    mma_bf16(O[nt], Al, bh0, bh1);
                    mma_bf16(O[nt], Ah, bl0, bl1);
                }
            }
        }
        __syncthreads();   // stage-2 reads done before next pass's prefetch
    }

    // ---- final epilogue: stage O [128 node][44], coalesced write ----
    float* Os = smf;
    {
        const int n0 = warp * 16 + ar;
        #pragma unroll
        for (int nt = 0; nt < 5; ++nt) {
            int col = nt * 8 + 2 * ac;
            *(float2*)(Os + n0 * 44 + col)       = make_float2(O[nt].x, O[nt].y);
            *(float2*)(Os + (n0 + 8) * 44 + col) = make_float2(O[nt].z, O[nt].w);
        }
    }
    __syncthreads();

    const float4* Os4 = (const float4*)Os;
    float4* out4 = (float4*)out;
    for (int i = t; i < 128 * 10; i += 256) {
        int n = i / 10, q = i - n * 10;
        int ngl = base + n;
        if (ngl < nNodes) out4[(size_t)ngl * 10 + q] = Os4[n * 11 + q];
    }
}

// -------- launch --------
extern "C" void kernel_launch(void* const* d_in, const int* in_sizes, int n_in,
                              void* d_out, int out_size)
{
    const float* feat = (const float*)d_in[0];
    const int*   ei   = (const int*)d_in[1];     // int32 (JAX x64 disabled)
    const float* W1  = (const float*)d_in[2];
    const float* b1  = (const float*)d_in[3];
    const float* W2  = (const float*)d_in[4];
    const float* b2  = (const float*)d_in[5];
    const float* Wm1 = (const float*)d_in[6];
    const float* bm1 = (const float*)d_in[7];
    const float* Wm2 = (const float*)d_in[8];
    const float* bm2 = (const float*)d_in[9];
    float* out = (float*)d_out;

    const int N = in_sizes[0] / 64;     // 100000
    const int E = in_sizes[1] / 2;      // 1600000

    float *agg, *h1, *h2, *wp;
    int *deg, *off, *cur, *csr, *bsum;
    cudaGetSymbolAddress((void**)&agg, g_agg);
    cudaGetSymbolAddress((void**)&h1,  g_h1);
    cudaGetSymbolAddress((void**)&h2,  g_h2);
    cudaGetSymbolAddress((void**)&wp,  g_wp);
    cudaGetSymbolAddress((void**)&deg, g_deg);
    cudaGetSymbolAddress((void**)&off, g_off);
    cudaGetSymbolAddress((void**)&cur, g_cur);
    cudaGetSymbolAddress((void**)&csr, g_csr);
    cudaGetSymbolAddress((void**)&bsum, g_bsum);

    const int SM_GEMM = SMF_TOTAL * 4;   // 73,728 B -> 2 blocks/SM
    cudaFuncSetAttribute(combine_kernel<128>, cudaFuncAttributeMaxDynamicSharedMemorySize, SM_GEMM);
    cudaFuncSetAttribute(combine_kernel<256>, cudaFuncAttributeMaxDynamicSharedMemorySize, SM_GEMM);
    cudaFuncSetAttribute(mlp_fused_kernel,    cudaFuncAttributeMaxDynamicSharedMemorySize, SM_GEMM);

    const int nodeBlocks = (N + 127) / 128;      // 782
    const int gatherBlocks = (N + 7) / 8;        // 12500
    const int scanBlocks = (N + 1023) / 1024;    // 98
    const int edgeBlocks = (E + 255) / 256;

    // ---- CSR build (once; reused by both layers) + W packing ----
    prep1_kernel<<<2048, 256>>>(deg, N, W1, W2, Wm1, Wm2, wp);
    hist_kernel<<<edgeBlocks, 256>>>(ei, deg, E, N);
    scan1_kernel<<<scanBlocks, 1024>>>(deg, off, bsum, N);
    scan3_kernel<<<scanBlocks, 1024>>>(off, cur, bsum, N);
    place_kernel<<<edgeBlocks, 256>>>(ei, cur, csr, E, N);

    // ---- Layer 1 ----
    gather64_kernel<<<gatherBlocks, 256>>>(off, deg, csr, feat, agg, N);
    combine_kernel<128><<<nodeBlocks, 256, SM_GEMM>>>(feat, agg, wp, b1, h1, N);
    // ---- Layer 2 ----
    gather128_kernel<<<gatherBlocks, 256>>>(off, deg, csr, h1, agg, N);
    combine_kernel<256><<<nodeBlocks, 256, SM_GEMM>>>(h1, agg, wp + 16384, b2, h2, N);
    // ---- MLP (fused: hidden layer never leaves the SM) ----
    mlp_fused_kernel<<<nodeBlocks, 256, SM_GEMM>>>(h2, wp + 49152, bm1,
                                                   wp + 81920, bm2, out, N);
}